// round 8
// baseline (speedup 1.0000x reference)
#include <cuda_runtime.h>
#include <cuda_fp16.h>
#include <cstdint>

#define NTOK 4096
#define DIM  1024
#define NH   16
#define HD   64

// Scratch (allocation-free rule: __device__ globals) — fp16 everywhere
__device__ __half g_q[NTOK * DIM];     // Q, pre-scaled by d^-0.5 * log2(e)
__device__ __half g_k[NTOK * DIM];     // K
__device__ __half g_att[NTOK * DIM];   // attention output
__device__ __half g_hx[NTOK * DIM];    // x in fp16
__device__ __half g_hqkv[DIM * 2048];  // w_qkv[:, 0:2048] packed dense fp16
__device__ __half g_hwo[DIM * DIM];    // w_out fp16

// ---------------------------------------------------------------------------
// helpers (base-ISA: mma.sync, ldmatrix, cp.async — all valid at target sm_100)
// ---------------------------------------------------------------------------
__device__ __forceinline__ uint32_t smem_u32(const void* p) {
    uint32_t a;
    asm("{ .reg .u64 t; cvta.to.shared.u64 t, %1; cvt.u32.u64 %0, t; }" : "=r"(a) : "l"(p));
    return a;
}
__device__ __forceinline__ uint32_t pack2(float a, float b) {
    __half2 h = __floats2half2_rn(a, b);
    return *reinterpret_cast<uint32_t*>(&h);
}
__device__ __forceinline__ float ex2(float x) {
    float r;
    asm("ex2.approx.f32 %0, %1;" : "=f"(r) : "f"(x));
    return r;
}
__device__ __forceinline__ void mma16(float* d, const uint32_t* a, uint32_t b0, uint32_t b1) {
    asm volatile(
        "mma.sync.aligned.m16n8k16.row.col.f32.f16.f16.f32 "
        "{%0,%1,%2,%3}, {%4,%5,%6,%7}, {%8,%9}, {%0,%1,%2,%3};"
        : "+f"(d[0]), "+f"(d[1]), "+f"(d[2]), "+f"(d[3])
        : "r"(a[0]), "r"(a[1]), "r"(a[2]), "r"(a[3]), "r"(b0), "r"(b1));
}
#define LDM_X4(r0, r1, r2, r3, addr)                                            \
    asm volatile("ldmatrix.sync.aligned.m8n8.x4.shared.b16 {%0,%1,%2,%3}, [%4];" \
                 : "=r"(r0), "=r"(r1), "=r"(r2), "=r"(r3) : "r"(addr))
#define LDM_X4T(r0, r1, r2, r3, addr)                                           \
    asm volatile("ldmatrix.sync.aligned.m8n8.x4.trans.shared.b16 {%0,%1,%2,%3}, [%4];" \
                 : "=r"(r0), "=r"(r1), "=r"(r2), "=r"(r3) : "r"(addr))
__device__ __forceinline__ void cp16(uint32_t dst, const void* src) {
    asm volatile("cp.async.cg.shared.global [%0], [%1], 16;" :: "r"(dst), "l"(src));
}
#define CP_COMMIT()  asm volatile("cp.async.commit_group;" ::: "memory")
#define CP_WAITG(n)  asm volatile("cp.async.wait_group %0;" :: "n"(n) : "memory")

#define ONES_H2 0x3C003C00u   // half2(1.0, 1.0)

// ===========================================================================
// Prepass: fp32 -> fp16 conversions (x, w_qkv[:, :2048] packed, w_out)
// ===========================================================================
__global__ void cvt_kernel(const float* __restrict__ x,
                           const float* __restrict__ wqkv,
                           const float* __restrict__ wout) {
    const int stride = gridDim.x * blockDim.x;
    int i = blockIdx.x * blockDim.x + threadIdx.x;
    for (int j = i; j < NTOK * DIM / 4; j += stride) {
        float4 v = reinterpret_cast<const float4*>(x)[j];
        reinterpret_cast<uint2*>(g_hx)[j] = make_uint2(pack2(v.x, v.y), pack2(v.z, v.w));
    }
    for (int j = i; j < DIM * 2048 / 4; j += stride) {
        int k = j >> 9, n4 = j & 511;
        float4 v = reinterpret_cast<const float4*>(wqkv)[k * 768 + n4];
        reinterpret_cast<uint2*>(g_hqkv)[j] = make_uint2(pack2(v.x, v.y), pack2(v.z, v.w));
    }
    for (int j = i; j < DIM * DIM / 4; j += stride) {
        float4 v = reinterpret_cast<const float4*>(wout)[j];
        reinterpret_cast<uint2*>(g_hwo)[j] = make_uint2(pack2(v.x, v.y), pack2(v.z, v.w));
    }
}

// ===========================================================================
// fp16 GEMM, 3-stage cp.async ring, ONE barrier per BK=32 step (as R7).
// ===========================================================================
#define GA_ST  10240
#define GB_ST  8704
#define GSTAGE (GA_ST + GB_ST)
#define GSMEM  (3 * GSTAGE)

template <int LDB>
__device__ __forceinline__ void gemm_body(
    const __half* __restrict__ Ah, const __half* __restrict__ Bh,
    int row0, int col0, char* dsm, float acc[4][4][4]) {
    const int tid = threadIdx.x, wid = tid >> 5, lane = tid & 31;
    const int wr = wid >> 2, wc = wid & 3;
    const uint32_t base = smem_u32(dsm);

    const __half* Asrc = Ah + (size_t)(row0 + (tid >> 1)) * DIM + (tid & 1) * 16;
    const __half* Bsrc = Bh + (size_t)(tid >> 3) * LDB + col0 + (tid & 7) * 16;
    const uint32_t Adst = base + (uint32_t)(tid >> 1) * 80 + (tid & 1) * 32;
    const uint32_t Bdst = base + GA_ST + (uint32_t)(tid >> 3) * 272 + (tid & 7) * 32;

    const uint32_t a_ld = base + (uint32_t)(wr * 64 + (lane & 15)) * 80 + ((lane >> 4) << 4);
    const uint32_t b_ld = base + GA_ST + (uint32_t)((lane & 7) + (lane & 8)) * 272 +
                          (uint32_t)(wc * 32) * 2 + ((lane >> 4) << 4);

#pragma unroll
    for (int s = 0; s < 2; s++) {
        cp16(Adst + s * GSTAGE, Asrc + s * 32);
        cp16(Adst + s * GSTAGE + 16, Asrc + s * 32 + 8);
        cp16(Bdst + s * GSTAGE, Bsrc + (size_t)(s * 32) * LDB);
        cp16(Bdst + s * GSTAGE + 16, Bsrc + (size_t)(s * 32) * LDB + 8);
        CP_COMMIT();
    }

    for (int it = 0; it < DIM / 32; it++) {
        CP_WAITG(1);
        __syncthreads();
        if (it + 2 < DIM / 32) {
            const int st = (it + 2) % 3;
            const int k0 = (it + 2) * 32;
            cp16(Adst + st * GSTAGE, Asrc + k0);
            cp16(Adst + st * GSTAGE + 16, Asrc + k0 + 8);
            cp16(Bdst + st * GSTAGE, Bsrc + (size_t)k0 * LDB);
            cp16(Bdst + st * GSTAGE + 16, Bsrc + (size_t)k0 * LDB + 8);
        }
        CP_COMMIT();

        const int st = it % 3;
        const uint32_t al = a_ld + st * GSTAGE;
        const uint32_t bl = b_ld + st * GSTAGE;
#pragma unroll
        for (int ks = 0; ks < 2; ks++) {
            uint32_t a[4][4];
#pragma unroll
            for (int mi = 0; mi < 4; mi++)
                LDM_X4(a[mi][0], a[mi][1], a[mi][2], a[mi][3],
                       al + (uint32_t)(mi * 16) * 80 + ks * 32);
#pragma unroll
            for (int p = 0; p < 2; p++) {
                uint32_t b0, b1, b2, b3;
                LDM_X4T(b0, b1, b2, b3, bl + (uint32_t)(ks * 16) * 272 + p * 32);
#pragma unroll
                for (int mi = 0; mi < 4; mi++) {
                    mma16(acc[mi][2 * p], a[mi], b0, b1);
                    mma16(acc[mi][2 * p + 1], a[mi], b2, b3);
                }
            }
        }
    }
}

__global__ __launch_bounds__(256, 2) void gemm_qk_tc() {
    extern __shared__ __align__(16) char dsm[];
    float acc[4][4][4];
#pragma unroll
    for (int mi = 0; mi < 4; mi++)
#pragma unroll
        for (int ni = 0; ni < 4; ni++)
#pragma unroll
            for (int j = 0; j < 4; j++) acc[mi][ni][j] = 0.f;

    const int row0 = blockIdx.y * 128, col0 = blockIdx.x * 128;
    gemm_body<2048>(g_hx, g_hqkv, row0, col0, dsm, acc);

    const int tid = threadIdx.x, wid = tid >> 5, lane = tid & 31;
    const int g = lane >> 2, tig = lane & 3;
    const int wr = wid >> 2, wc = wid & 3;
    const bool  isq   = (col0 < DIM);
    const float scale = isq ? 0.18033688011112042f : 1.0f;  // d^-0.5 * log2(e)
    __half* Out = isq ? g_q : g_k;
    const int oc0 = isq ? col0 : col0 - DIM;
#pragma unroll
    for (int mi = 0; mi < 4; mi++)
#pragma unroll
        for (int ni = 0; ni < 4; ni++) {
            const int r = row0 + wr * 64 + mi * 16 + g;
            const int c = oc0 + wc * 32 + ni * 8 + 2 * tig;
            *reinterpret_cast<uint32_t*>(&Out[(size_t)r * DIM + c]) =
                pack2(acc[mi][ni][0] * scale, acc[mi][ni][1] * scale);
            *reinterpret_cast<uint32_t*>(&Out[(size_t)(r + 8) * DIM + c]) =
                pack2(acc[mi][ni][2] * scale, acc[mi][ni][3] * scale);
        }
}

__global__ __launch_bounds__(256, 2) void gemm_out_tc(const float* __restrict__ bias,
                                                      float* __restrict__ C) {
    extern __shared__ __align__(16) char dsm[];
    float acc[4][4][4];
#pragma unroll
    for (int mi = 0; mi < 4; mi++)
#pragma unroll
        for (int ni = 0; ni < 4; ni++)
#pragma unroll
            for (int j = 0; j < 4; j++) acc[mi][ni][j] = 0.f;

    const int row0 = blockIdx.y * 128, col0 = blockIdx.x * 128;
    gemm_body<DIM>(g_att, g_hwo, row0, col0, dsm, acc);

    const int tid = threadIdx.x, wid = tid >> 5, lane = tid & 31;
    const int g = lane >> 2, tig = lane & 3;
    const int wr = wid >> 2, wc = wid & 3;
#pragma unroll
    for (int mi = 0; mi < 4; mi++)
#pragma unroll
        for (int ni = 0; ni < 4; ni++) {
            const int r = row0 + wr * 64 + mi * 16 + g;
            const int c = col0 + wc * 32 + ni * 8 + 2 * tig;
            const float b0 = bias[c], b1 = bias[c + 1];
            *reinterpret_cast<float2*>(&C[(size_t)r * DIM + c]) =
                make_float2(acc[mi][ni][0] + b0, acc[mi][ni][1] + b1);
            *reinterpret_cast<float2*>(&C[(size_t)(r + 8) * DIM + c]) =
                make_float2(acc[mi][ni][2] + b0, acc[mi][ni][3] + b1);
        }
}

// ===========================================================================
// fp16 attention, P-in-registers, 6-stage cp.async K ring, ONE barrier per
// TWO k-tiles (128 keys). Rowsum via ones-mma (no FADD chain, no shuffles).
// Block = 128 q x 1 head, 8 warps x 16 q rows. V := K (reference bug).
// ===========================================================================
#define KST 9216                              // one K stage: 64 rows x 144 B
#define ATT_KSTAGES (6 * KST)                 // 55296
#define ATT_SMEM (ATT_KSTAGES + 128 * 144)    // + Q tile = 73728 B

__global__ __launch_bounds__(256, 2) void attn_tc() {
    extern __shared__ __align__(16) char dsm[];
    const uint32_t sK_b = smem_u32(dsm);
    const uint32_t sQ_b = sK_b + ATT_KSTAGES;

    const int tid = threadIdx.x, wid = tid >> 5, lane = tid & 31;
    const int h = blockIdx.y, q0 = blockIdx.x * 128;
    const int m0 = wid * 16;
    const int g = lane >> 2, tig = lane & 3;

    const uint32_t qa_ld = sQ_b + (uint32_t)(m0 + (lane & 15)) * 144 + ((lane >> 4) << 4);
    const uint32_t bs_ld = sK_b + (uint32_t)((lane & 7) + ((lane & 16) >> 1)) * 144 + ((lane & 8) << 1);
    const uint32_t bo_ld = sK_b + (uint32_t)((lane & 7) + (lane & 8)) * 144 + ((lane >> 4) << 4);

    const __half* Ksrc = &g_k[(size_t)(tid >> 2) * DIM + h * HD + (tid & 3) * 16];
    const uint32_t Kdst = sK_b + (uint32_t)(tid >> 2) * 144 + (tid & 3) * 32;

    // Stage Q tile [128 x 64] into sQ
#pragma unroll
    for (int c = 0; c < 4; c++) {
        int fid = c * 256 + tid;
        int r = fid >> 3, u = fid & 7;
        uint4 v = *reinterpret_cast<const uint4*>(
            &g_q[(size_t)(q0 + r) * DIM + h * HD + u * 8]);
        *reinterpret_cast<uint4*>(dsm + ATT_KSTAGES + r * 144 + u * 16) = v;
    }
    // prologue: K tiles 0..3 -> stages 0..3, one commit group per PAIR
#pragma unroll
    for (int s = 0; s < 4; s++) {
        const __half* src = Ksrc + (size_t)s * 64 * DIM;
        cp16(Kdst + s * KST, src);
        cp16(Kdst + s * KST + 16, src + 8);
        if (s & 1) CP_COMMIT();
    }
    __syncthreads();

    uint32_t qf[4][4];
#pragma unroll
    for (int ks = 0; ks < 4; ks++)
        LDM_X4(qf[ks][0], qf[ks][1], qf[ks][2], qf[ks][3], qa_ld + ks * 32);

    float o[8][4];
#pragma unroll
    for (int ni = 0; ni < 8; ni++)
#pragma unroll
        for (int j = 0; j < 4; j++) o[ni][j] = 0.f;
    float rsacc[4] = {0.f, 0.f, 0.f, 0.f};   // rowsum accumulator (P @ ones)

    for (int it = 0; it < 32; it++) {        // pair of k-tiles per iteration
        CP_WAITG(1);
        __syncthreads();
        if (it + 2 < 32) {
#pragma unroll
            for (int s = 0; s < 2; s++) {
                const int kt2 = 2 * it + 4 + s;
                const __half* src = Ksrc + (size_t)kt2 * 64 * DIM;
                const uint32_t d = Kdst + (uint32_t)(2 * ((it + 2) % 3) + s) * KST;
                cp16(d, src);
                cp16(d + 16, src + 8);
            }
        }
        CP_COMMIT();

#pragma unroll
        for (int half = 0; half < 2; half++) {
            const int st = 2 * (it % 3) + half;
            const uint32_t bsl = bs_ld + st * KST;
            const uint32_t bol = bo_ld + st * KST;

            // S = Q @ K^T  (fp32 frags)
            float s[8][4];
#pragma unroll
            for (int ni = 0; ni < 8; ni++)
#pragma unroll
                for (int j = 0; j < 4; j++) s[ni][j] = 0.f;
#pragma unroll
            for (int ks = 0; ks < 4; ks++) {
#pragma unroll
                for (int p = 0; p < 4; p++) {
                    uint32_t b0, b1, b2, b3;
                    LDM_X4(b0, b1, b2, b3, bsl + (uint32_t)(16 * p) * 144 + ks * 32);
                    mma16(s[2 * p], qf[ks], b0, b1);
                    mma16(s[2 * p + 1], qf[ks], b2, b3);
                }
            }

            // P = 2^S (register A-frags), rowsum via ones-mma, O += P @ K
#pragma unroll
            for (int ks = 0; ks < 4; ks++) {
                uint32_t a[4];
                a[0] = pack2(ex2(s[2 * ks][0]), ex2(s[2 * ks][1]));
                a[1] = pack2(ex2(s[2 * ks][2]), ex2(s[2 * ks][3]));
                a[2] = pack2(ex2(s[2 * ks + 1][0]), ex2(s[2 * ks + 1][1]));
                a[3] = pack2(ex2(s[2 * ks + 1][2]), ex2(s[2 * ks + 1][3]));
                mma16(rsacc, a, ONES_H2, ONES_H2);
#pragma unroll
                for (int p = 0; p < 4; p++) {
                    uint32_t b0, b1, b2, b3;
                    LDM_X4T(b0, b1, b2, b3, bol + (uint32_t)(16 * ks) * 144 + p * 32);
                    mma16(o[2 * p], a, b0, b1);
                    mma16(o[2 * p + 1], a, b2, b3);
                }
            }
        }
    }

    // rsacc[0] = full rowsum(row g), rsacc[2] = rowsum(row g+8) — no shuffles
    const float inv0 = 1.f / rsacc[0], inv1 = 1.f / rsacc[2];

#pragma unroll
    for (int ni = 0; ni < 8; ni++) {
        const int r = q0 + m0 + g;
        const int c = h * HD + ni * 8 + 2 * tig;
        *reinterpret_cast<uint32_t*>(&g_att[(size_t)r * DIM + c]) =
            pack2(o[ni][0] * inv0, o[ni][1] * inv0);
        *reinterpret_cast<uint32_t*>(&g_att[(size_t)(r + 8) * DIM + c]) =
            pack2(o[ni][2] * inv1, o[ni][3] * inv1);
    }
}

// ===========================================================================
extern "C" void kernel_launch(void* const* d_in, const int* in_sizes, int n_in,
                              void* d_out, int out_size) {
    const float *x = nullptr, *wqkv = nullptr, *wout = nullptr, *bout = nullptr;
    for (int i = 0; i < n_in; i++) {
        const float* p = (const float*)d_in[i];
        if      (in_sizes[i] == NTOK * DIM)    x    = p;
        else if (in_sizes[i] == DIM * 3 * DIM) wqkv = p;
        else if (in_sizes[i] == DIM * DIM)     wout = p;
        else if (in_sizes[i] == DIM)           bout = p;
    }
    float* out = (float*)d_out;

    cudaFuncSetAttribute((const void*)gemm_qk_tc,
                         cudaFuncAttributeMaxDynamicSharedMemorySize, GSMEM);
    cudaFuncSetAttribute((const void*)gemm_out_tc,
                         cudaFuncAttributeMaxDynamicSharedMemorySize, GSMEM);
    cudaFuncSetAttribute((const void*)attn_tc,
                         cudaFuncAttributeMaxDynamicSharedMemorySize, ATT_SMEM);

    cvt_kernel<<<1024, 256>>>(x, wqkv, wout);                    // fp32 -> fp16 prepass
    gemm_qk_tc<<<dim3(16, 32), 256, GSMEM>>>();                  // Q (pre-scaled) + K
    attn_tc<<<dim3(32, 16), 256, ATT_SMEM>>>();                  // fp16 mma attention
    gemm_out_tc<<<dim3(8, 32), 256, GSMEM>>>(bout, out);         // att @ w_out + b_out
}